// round 5
// baseline (speedup 1.0000x reference)
#include <cuda_runtime.h>

#define T_LEN 1024
#define S_LEN 1024
#define BSZ   4
#define EMB   1024
#define NH    16
#define HD    64
#define MTOK  (T_LEN*BSZ)   // 4096 tokens

typedef unsigned long long u64;

// ---------------------------------------------------------------------------
// Scratch (static __device__ arrays: allocation-free, graph-safe)
// ---------------------------------------------------------------------------
__device__ float g_q [(size_t)MTOK * EMB];                 //  16 MB
__device__ float g_kv[(size_t)MTOK * 2 * EMB];             //  32 MB
__device__ float g_p [(size_t)BSZ * NH * T_LEN * S_LEN];   // 256 MB (scores -> probs in place)
__device__ float g_ao[(size_t)MTOK * EMB];                 //  16 MB

// ---------------------------------------------------------------------------
// Packed dual-FMA: d.lo = a.lo*b.lo + d.lo ; d.hi = a.hi*b.hi + d.hi
// (FFMA2 — only reachable via PTX; scalar FFMA is half-rate on sm_103a)
// ---------------------------------------------------------------------------
__device__ __forceinline__ void fma2(u64& d, u64 a, u64 b) {
    asm("fma.rn.f32x2 %0, %1, %2, %3;" : "=l"(d) : "l"(a), "l"(b), "l"(d));
}

// ---------------------------------------------------------------------------
// Fast exp (FMA polynomial, rel err ~2e-7; valid for x <= 0)
// ---------------------------------------------------------------------------
__device__ __forceinline__ float fast_exp(float x) {
    float t = x * 1.4426950408889634f;
    t = fmaxf(t, -126.0f);
    int   i = __float2int_rn(t);
    float f = t - (float)i;
    float p = 1.5403530e-4f;
    p = fmaf(p, f, 1.3333558e-3f);
    p = fmaf(p, f, 9.6181291e-3f);
    p = fmaf(p, f, 5.5504109e-2f);
    p = fmaf(p, f, 2.4022651e-1f);
    p = fmaf(p, f, 6.9314718e-1f);
    p = fmaf(p, f, 1.0f);
    return p * __int_as_float((i + 127) << 23);
}

// ---------------------------------------------------------------------------
// Strided/batched fp32 SGEMM with packed-f32x2 mainloop.
//   BKM=true : C[m,n] = sum_k A[m,k] * B[n,k]   (projections / scores)
//   BKM=false: C[m,n] = sum_k A[m,k] * B[k,n]   (attn @ V)
// B tile stored DUPLICATED in smem (Bs2[k][2n]=Bs2[k][2n+1]=b) so the {b,b}
// fragment for FFMA2 is a plain 8B vector load; A fragments pack two adjacent
// m rows (naturally contiguous in As). Epilogue: C = (acc + bias[n]) * scale.
// All dims are multiples of the tile sizes for this problem.
// ---------------------------------------------------------------------------
template<int BM, int BN, int BK, int TM, int TN, bool BKM>
__global__ __launch_bounds__((BM/TM)*(BN/TN), 2)
void sgemm(const float* __restrict__ A, const float* __restrict__ Bm,
           float* __restrict__ C,
           int M, int N, int K, int lda, int ldb, int ldc,
           long long aB, long long aH, long long bB, long long bH,
           long long cB, long long cH, int nH,
           const float* __restrict__ bias, float scale)
{
    constexpr int THREADS = (BM/TM)*(BN/TN);
    constexpr int KV4 = BK/4;
    constexpr int TMH = TM/2;

    const int z  = blockIdx.z;
    const int bb = z / nH;
    const int hh = z - bb * nH;
    A  += aB*bb + aH*hh;
    Bm += bB*bb + bH*hh;
    C  += cB*bb + cH*hh;

    __shared__ float As [BK][BM + 4];
    __shared__ float Bs2[BK][2*BN + 8];   // duplicated pairs

    const int tid  = threadIdx.x;
    const int m0   = blockIdx.y * BM;
    const int n0   = blockIdx.x * BN;
    const int tRow = (tid / (BN/TN)) * TM;
    const int tCol = (tid % (BN/TN)) * TN;

    u64 accp[TMH][TN];
#pragma unroll
    for (int ip = 0; ip < TMH; ip++)
#pragma unroll
        for (int j = 0; j < TN; j++) accp[ip][j] = 0ull;

    for (int kt = 0; kt < K; kt += BK) {
        // ---- stage A tile: As[k][m] ----
#pragma unroll
        for (int ld = 0; ld < (BM*BK)/(THREADS*4); ld++) {
            int e  = tid + ld*THREADS;
            int r  = e / KV4;
            int kc = e - r*KV4;
            float4 v = *(const float4*)(A + (long long)(m0 + r)*lda + kt + kc*4);
            As[kc*4+0][r] = v.x; As[kc*4+1][r] = v.y;
            As[kc*4+2][r] = v.z; As[kc*4+3][r] = v.w;
        }
        // ---- stage B tile (duplicated): Bs2[k][2n]=Bs2[k][2n+1]=b ----
        if constexpr (BKM) {
#pragma unroll
            for (int ld = 0; ld < (BN*BK)/(THREADS*4); ld++) {
                int e  = tid + ld*THREADS;
                int r  = e / KV4;
                int kc = e - r*KV4;
                float4 v = *(const float4*)(Bm + (long long)(n0 + r)*ldb + kt + kc*4);
                *(float2*)&Bs2[kc*4+0][2*r] = make_float2(v.x, v.x);
                *(float2*)&Bs2[kc*4+1][2*r] = make_float2(v.y, v.y);
                *(float2*)&Bs2[kc*4+2][2*r] = make_float2(v.z, v.z);
                *(float2*)&Bs2[kc*4+3][2*r] = make_float2(v.w, v.w);
            }
        } else {
#pragma unroll
            for (int ld = 0; ld < (BK*BN)/(THREADS*4); ld++) {
                int e  = tid + ld*THREADS;
                int r  = e / (BN/4);
                int nc = e - r*(BN/4);
                float4 v = *(const float4*)(Bm + (long long)(kt + r)*ldb + n0 + nc*4);
                float4 lo = make_float4(v.x, v.x, v.y, v.y);
                float4 hi = make_float4(v.z, v.z, v.w, v.w);
                *(float4*)&Bs2[r][8*nc + 0] = lo;
                *(float4*)&Bs2[r][8*nc + 4] = hi;
            }
        }
        __syncthreads();

        // ---- packed-FMA mainloop ----
#pragma unroll
        for (int kk = 0; kk < BK; kk++) {
            u64 a2[TMH], b2[TN];
#pragma unroll
            for (int ip = 0; ip < TMH; ip++)
                a2[ip] = *(const u64*)&As[kk][tRow + 2*ip];
#pragma unroll
            for (int j = 0; j < TN; j++)
                b2[j] = *(const u64*)&Bs2[kk][2*(tCol + j)];
#pragma unroll
            for (int ip = 0; ip < TMH; ip++)
#pragma unroll
                for (int j = 0; j < TN; j++)
                    fma2(accp[ip][j], a2[ip], b2[j]);
        }
        __syncthreads();
    }

    // ---- epilogue: unpack, bias + scale, vectorized stores ----
#pragma unroll
    for (int ip = 0; ip < TMH; ip++) {
#pragma unroll
        for (int half = 0; half < 2; half++) {
            int i = 2*ip + half;
#pragma unroll
            for (int j4 = 0; j4 < TN; j4 += 4) {
                int n = n0 + tCol + j4;
                float4 bv = bias ? *(const float4*)(bias + n)
                                 : make_float4(0.f, 0.f, 0.f, 0.f);
                float a0 = half ? ((float2*)&accp[ip][j4+0])->y : ((float2*)&accp[ip][j4+0])->x;
                float a1 = half ? ((float2*)&accp[ip][j4+1])->y : ((float2*)&accp[ip][j4+1])->x;
                float a2v= half ? ((float2*)&accp[ip][j4+2])->y : ((float2*)&accp[ip][j4+2])->x;
                float a3 = half ? ((float2*)&accp[ip][j4+3])->y : ((float2*)&accp[ip][j4+3])->x;
                float4 o;
                o.x = (a0 + bv.x) * scale;
                o.y = (a1 + bv.y) * scale;
                o.z = (a2v+ bv.z) * scale;
                o.w = (a3 + bv.w) * scale;
                *(float4*)(C + (long long)(m0 + tRow + i)*ldc + n) = o;
            }
        }
    }
}

// ---------------------------------------------------------------------------
// Fused softmax * mask + avg-over-heads (in place on scores buffer).
// ---------------------------------------------------------------------------
__global__ __launch_bounds__(256)
void softmax_kernel(float* __restrict__ P,
                    const float* __restrict__ mask,
                    float* __restrict__ avg)
{
    const int t   = blockIdx.x;
    const int b   = blockIdx.y;
    const int tid = threadIdx.x;
    const int s0  = tid * 4;
    __shared__ float red[8];

    const float4 mk = *(const float4*)(mask + ((long long)b*T_LEN + t)*S_LEN + s0);
    float avx = 0.f, avy = 0.f, avz = 0.f, avw = 0.f;

    for (int h = 0; h < NH; ++h) {
        float* row = P + ((long long)(b*NH + h)*T_LEN + t)*S_LEN;
        float4 r = *(const float4*)(row + s0);

        float mx = fmaxf(fmaxf(r.x, r.y), fmaxf(r.z, r.w));
#pragma unroll
        for (int o = 16; o; o >>= 1) mx = fmaxf(mx, __shfl_xor_sync(0xffffffffu, mx, o));
        if ((tid & 31) == 0) red[tid >> 5] = mx;
        __syncthreads();
        mx = red[0];
#pragma unroll
        for (int w = 1; w < 8; w++) mx = fmaxf(mx, red[w]);
        __syncthreads();

        float4 e;
        e.x = fast_exp(r.x - mx); e.y = fast_exp(r.y - mx);
        e.z = fast_exp(r.z - mx); e.w = fast_exp(r.w - mx);
        float sm = (e.x + e.y) + (e.z + e.w);
#pragma unroll
        for (int o = 16; o; o >>= 1) sm += __shfl_xor_sync(0xffffffffu, sm, o);
        if ((tid & 31) == 0) red[tid >> 5] = sm;
        __syncthreads();
        sm = ((red[0] + red[1]) + (red[2] + red[3]))
           + ((red[4] + red[5]) + (red[6] + red[7]));
        __syncthreads();

        float inv = 1.0f / sm;
        float4 pv;
        pv.x = e.x * inv * mk.x; pv.y = e.y * inv * mk.y;
        pv.z = e.z * inv * mk.z; pv.w = e.w * inv * mk.w;
        *(float4*)(row + s0) = pv;
        avx += pv.x; avy += pv.y; avz += pv.z; avw += pv.w;
    }

    const float k = 1.0f / (float)NH;
    float4 o = make_float4(avx*k, avy*k, avz*k, avw*k);
    *(float4*)(avg + ((long long)b*T_LEN + t)*S_LEN + s0) = o;
}

// ---------------------------------------------------------------------------
// Launch orchestration.
// Inputs (metadata order): query, key, hard_attention, in_proj_weight,
//                          in_proj_bias, out_proj_weight, out_proj_bias
// Output: out (T,B,E) fp32 followed by avg_weights (B,T,S) fp32.
// ---------------------------------------------------------------------------
extern "C" void kernel_launch(void* const* d_in, const int* in_sizes, int n_in,
                              void* d_out, int out_size)
{
    (void)in_sizes; (void)n_in; (void)out_size;
    const float* query = (const float*)d_in[0];
    const float* key   = (const float*)d_in[1];
    const float* mask  = (const float*)d_in[2];
    const float* wIn   = (const float*)d_in[3];
    const float* bIn   = (const float*)d_in[4];
    const float* wOut  = (const float*)d_in[5];
    const float* bOut  = (const float*)d_in[6];

    float* out = (float*)d_out;
    float* avg = out + (size_t)T_LEN * BSZ * EMB;

    float *q, *kv, *p, *ao;
    cudaGetSymbolAddress((void**)&q,  g_q);
    cudaGetSymbolAddress((void**)&kv, g_kv);
    cudaGetSymbolAddress((void**)&p,  g_p);
    cudaGetSymbolAddress((void**)&ao, g_ao);

    const float scaling = 0.125f;   // 64^-0.5

    // 1) Q = (query @ Wq^T + bq) * scaling
    sgemm<128,128,16,8,8,true><<<dim3(EMB/128, MTOK/128, 1), 256>>>(
        query, wIn, q, MTOK, EMB, EMB, EMB, EMB, EMB,
        0,0,0,0,0,0, 1, bIn, scaling);

    // 2) KV = key @ Wkv^T + bkv
    sgemm<128,128,16,8,8,true><<<dim3(2*EMB/128, MTOK/128, 1), 256>>>(
        key, wIn + (size_t)EMB*EMB, kv, MTOK, 2*EMB, EMB, EMB, EMB, 2*EMB,
        0,0,0,0,0,0, 1, bIn + EMB, 1.0f);

    // 3) scores[b,h] = Q_bh @ K_bh^T   (K=64, 64 batches)
    sgemm<128,128,16,8,8,true><<<dim3(S_LEN/128, T_LEN/128, BSZ*NH), 256>>>(
        q, kv, p, T_LEN, S_LEN, HD,
        BSZ*EMB, BSZ*2*EMB, S_LEN,
        (long long)EMB, (long long)HD,
        (long long)2*EMB, (long long)HD,
        (long long)NH*T_LEN*S_LEN, (long long)T_LEN*S_LEN,
        NH, nullptr, 1.0f);

    // 4) softmax * mask, avg over heads
    softmax_kernel<<<dim3(T_LEN, BSZ), 256>>>(p, mask, avg);

    // 5) attn_out[b,h] = P_bh @ V_bh   (N=64, K=1024, 64 batches)
    sgemm<128,64,16,8,4,false><<<dim3(1, T_LEN/128, BSZ*NH), 256>>>(
        p, kv + EMB, ao, T_LEN, HD, S_LEN,
        S_LEN, BSZ*2*EMB, BSZ*EMB,
        (long long)NH*T_LEN*S_LEN, (long long)T_LEN*S_LEN,
        (long long)2*EMB, (long long)HD,
        (long long)EMB, (long long)HD,
        NH, nullptr, 1.0f);

    // 6) out = attn_out @ Wout^T + bout
    sgemm<128,128,16,8,8,true><<<dim3(EMB/128, MTOK/128, 1), 256>>>(
        ao, wOut, out, MTOK, EMB, EMB, EMB, EMB, EMB,
        0,0,0,0,0,0, 1, bOut, 1.0f);
}